// round 1
// baseline (speedup 1.0000x reference)
#include <cuda_runtime.h>
#include <math.h>

// Problem constants (fixed shapes for this problem instance)
#define Bb 4
#define Cc 512
#define NN 4096          // H*W
#define GG 32            // num groups
#define CPG (Cc / GG)    // channels per group = 16

// ---------------- scratch (device globals; no allocation allowed) ----------
__device__ float g_h [Bb * Cc * NN];   // groupnorm output  [B, C, N]
__device__ float g_q [Bb * Cc * NN];
__device__ float g_k [Bb * Cc * NN];
__device__ float g_v [Bb * Cc * NN];
__device__ float g_ao[Bb * Cc * NN];   // attention output  [B, C, N]
__device__ float g_s [(size_t)Bb * NN * NN]; // scores/attn [B, N, N]

// ---------------- block reductions ------------------------------------------
__device__ __forceinline__ float block_sum(float v, float* sh) {
    int lane = threadIdx.x & 31, w = threadIdx.x >> 5;
    #pragma unroll
    for (int o = 16; o; o >>= 1) v += __shfl_down_sync(0xffffffffu, v, o);
    if (!lane) sh[w] = v;
    __syncthreads();
    int nw = blockDim.x >> 5;
    v = (threadIdx.x < nw) ? sh[threadIdx.x] : 0.f;
    if (w == 0) {
        #pragma unroll
        for (int o = 16; o; o >>= 1) v += __shfl_down_sync(0xffffffffu, v, o);
        if (!lane) sh[0] = v;
    }
    __syncthreads();
    float r = sh[0];
    __syncthreads();
    return r;
}

__device__ __forceinline__ float block_max(float v, float* sh) {
    int lane = threadIdx.x & 31, w = threadIdx.x >> 5;
    #pragma unroll
    for (int o = 16; o; o >>= 1) v = fmaxf(v, __shfl_down_sync(0xffffffffu, v, o));
    if (!lane) sh[w] = v;
    __syncthreads();
    int nw = blockDim.x >> 5;
    v = (threadIdx.x < nw) ? sh[threadIdx.x] : -INFINITY;
    if (w == 0) {
        #pragma unroll
        for (int o = 16; o; o >>= 1) v = fmaxf(v, __shfl_down_sync(0xffffffffu, v, o));
        if (!lane) sh[0] = v;
    }
    __syncthreads();
    float r = sh[0];
    __syncthreads();
    return r;
}

// ---------------- GroupNorm --------------------------------------------------
// one block per (b, g); reduces over CPG*N = 65536 elements
__global__ __launch_bounds__(256) void groupnorm_kernel(
    const float* __restrict__ x, const float* __restrict__ gamma,
    const float* __restrict__ beta, float* __restrict__ h)
{
    __shared__ float sh[32];
    int b = blockIdx.x / GG;
    int g = blockIdx.x % GG;
    const long base = ((long)b * Cc + (long)g * CPG) * NN;
    const long len  = (long)CPG * NN;  // 65536

    float s = 0.f, ss = 0.f;
    for (long i = threadIdx.x; i < len; i += blockDim.x) {
        float v = x[base + i];
        s += v; ss += v * v;
    }
    s  = block_sum(s,  sh);
    ss = block_sum(ss, sh);
    float mean = s / (float)len;
    float var  = ss / (float)len - mean * mean;
    float inv  = rsqrtf(var + 1e-6f);

    for (long i = threadIdx.x; i < len; i += blockDim.x) {
        int c = g * CPG + (int)(i / NN);
        h[base + i] = (x[base + i] - mean) * inv * gamma[c] + beta[c];
    }
}

// ---------------- generic tiled SGEMM ---------------------------------------
// C[m,n] = alpha * sum_k opA(A)[m,k] * opB(B)[n? ...] (+bias[m]) (+res[m,n])
// OPA=0: A is [M,K] row-major.   OPA=1: A is [K,M] row-major (A^T used).
// OPB=0: B is [K,N] row-major.   OPB=1: B is [N,K] row-major (B^T used).
// All of M, N divisible by 128; K divisible by 16 (guaranteed by shapes).
#define BM 128
#define BN 128
#define BKk 16
#define TM 8
#define TN 8

template<int OPA, int OPB, bool BIAS, bool RES>
__global__ __launch_bounds__(256) void gemm_kernel(
    const float* __restrict__ A, long sA,
    const float* __restrict__ Bm, long sB,
    const float* __restrict__ bias,
    const float* __restrict__ res, long sR,
    float* __restrict__ C, long sC,
    int M, int N, int K, float alpha)
{
    const int bz = blockIdx.z;
    A  += (long)bz * sA;
    Bm += (long)bz * sB;
    C  += (long)bz * sC;
    if (RES) res += (long)bz * sR;

    const int m0 = blockIdx.y * BM;
    const int n0 = blockIdx.x * BN;

    __shared__ float As[BKk][BM + 4];
    __shared__ float Bs[BKk][BN + 4];

    const int tid  = threadIdx.x;
    const int tcol = tid % (BN / TN);   // 0..15
    const int trow = tid / (BN / TN);   // 0..15

    float acc[TM][TN];
    #pragma unroll
    for (int i = 0; i < TM; i++)
        #pragma unroll
        for (int j = 0; j < TN; j++) acc[i][j] = 0.f;

    float ar[TM], br[TN];

    for (int k0 = 0; k0 < K; k0 += BKk) {
        // ---- load A tile into As[k][m] ----
        if (OPA == 0) {
            // A[M,K]: each thread loads one float4 along k, stores transposed
            const int kq   = tid % 4;       // float4 idx along k
            const int mrow = tid / 4;       // 0..63
            #pragma unroll
            for (int p = 0; p < 2; p++) {
                int m = mrow + p * 64;
                float4 v = *(const float4*)(A + (long)(m0 + m) * K + k0 + kq * 4);
                As[kq * 4 + 0][m] = v.x;
                As[kq * 4 + 1][m] = v.y;
                As[kq * 4 + 2][m] = v.z;
                As[kq * 4 + 3][m] = v.w;
            }
        } else {
            // A[K,M]: rows k, coalesced float4 along m, direct store
            const int jq = tid % 32;        // float4 idx along m
            const int i0 = tid / 32;        // 0..7
            #pragma unroll
            for (int p = 0; p < 2; p++) {
                int ii = i0 + p * 8;
                float4 v = *(const float4*)(A + (long)(k0 + ii) * M + m0 + jq * 4);
                *(float4*)&As[ii][jq * 4] = v;
            }
        }
        // ---- load B tile into Bs[k][n] ----
        if (OPB == 0) {
            const int jq = tid % 32;
            const int i0 = tid / 32;
            #pragma unroll
            for (int p = 0; p < 2; p++) {
                int ii = i0 + p * 8;
                float4 v = *(const float4*)(Bm + (long)(k0 + ii) * N + n0 + jq * 4);
                *(float4*)&Bs[ii][jq * 4] = v;
            }
        } else {
            // B[N,K]
            const int kq   = tid % 4;
            const int nrow = tid / 4;
            #pragma unroll
            for (int p = 0; p < 2; p++) {
                int n = nrow + p * 64;
                float4 v = *(const float4*)(Bm + (long)(n0 + n) * K + k0 + kq * 4);
                Bs[kq * 4 + 0][n] = v.x;
                Bs[kq * 4 + 1][n] = v.y;
                Bs[kq * 4 + 2][n] = v.z;
                Bs[kq * 4 + 3][n] = v.w;
            }
        }
        __syncthreads();

        #pragma unroll
        for (int kk = 0; kk < BKk; kk++) {
            *(float4*)&ar[0] = *(const float4*)&As[kk][trow * TM];
            *(float4*)&ar[4] = *(const float4*)&As[kk][trow * TM + 4];
            *(float4*)&br[0] = *(const float4*)&Bs[kk][tcol * TN];
            *(float4*)&br[4] = *(const float4*)&Bs[kk][tcol * TN + 4];
            #pragma unroll
            for (int i = 0; i < TM; i++)
                #pragma unroll
                for (int j = 0; j < TN; j++)
                    acc[i][j] = fmaf(ar[i], br[j], acc[i][j]);
        }
        __syncthreads();
    }

    // ---- epilogue ----
    #pragma unroll
    for (int i = 0; i < TM; i++) {
        int m = m0 + trow * TM + i;
        float bv = BIAS ? bias[m] : 0.f;
        long base = (long)m * N + n0 + tcol * TN;
        #pragma unroll
        for (int j = 0; j < TN; j++) {
            float r = acc[i][j] * alpha + bv;
            if (RES) r += res[base + j];
            C[base + j] = r;
        }
    }
}

// ---------------- row softmax -------------------------------------------------
// one block per row of [B*N, N]
__global__ __launch_bounds__(256) void softmax_kernel(float* __restrict__ s)
{
    __shared__ float sh[32];
    float* p = s + (size_t)blockIdx.x * NN;

    float m = -INFINITY;
    for (int j = threadIdx.x; j < NN; j += 256) m = fmaxf(m, p[j]);
    m = block_max(m, sh);

    float sum = 0.f;
    for (int j = threadIdx.x; j < NN; j += 256) {
        float e = __expf(p[j] - m);
        p[j] = e;
        sum += e;
    }
    sum = block_sum(sum, sh);
    float inv = 1.f / sum;
    for (int j = threadIdx.x; j < NN; j += 256) p[j] *= inv;
}

// ---------------- launch -------------------------------------------------------
extern "C" void kernel_launch(void* const* d_in, const int* in_sizes, int n_in,
                              void* d_out, int out_size)
{
    const float* x     = (const float*)d_in[0];
    const float* gamma = (const float*)d_in[1];
    const float* beta  = (const float*)d_in[2];
    const float* wq    = (const float*)d_in[3];
    const float* bq    = (const float*)d_in[4];
    const float* wk    = (const float*)d_in[5];
    const float* bk    = (const float*)d_in[6];
    const float* wv    = (const float*)d_in[7];
    const float* bv    = (const float*)d_in[8];
    const float* wo    = (const float*)d_in[9];
    const float* bo    = (const float*)d_in[10];
    float* out = (float*)d_out;

    float* h;  cudaGetSymbolAddress((void**)&h,  g_h);
    float* q;  cudaGetSymbolAddress((void**)&q,  g_q);
    float* k;  cudaGetSymbolAddress((void**)&k,  g_k);
    float* v;  cudaGetSymbolAddress((void**)&v,  g_v);
    float* ao; cudaGetSymbolAddress((void**)&ao, g_ao);
    float* sc; cudaGetSymbolAddress((void**)&sc, g_s);

    const long CN = (long)Cc * NN;      // per-batch [C,N] stride
    const long NN2 = (long)NN * NN;     // per-batch [N,N] stride
    const float scale = 1.0f / sqrtf((float)Cc);

    // 1) GroupNorm
    groupnorm_kernel<<<Bb * GG, 256>>>(x, gamma, beta, h);

    // 2) Q,K,V projections: C[d,i] = W[d,c] * h[b,c,i] + bias[d]
    dim3 gproj(NN / BN, Cc / BM, Bb);
    gemm_kernel<0,0,true,false><<<gproj, 256>>>(wq, 0, h, CN, bq, nullptr, 0, q, CN, Cc, NN, Cc, 1.0f);
    gemm_kernel<0,0,true,false><<<gproj, 256>>>(wk, 0, h, CN, bk, nullptr, 0, k, CN, Cc, NN, Cc, 1.0f);
    gemm_kernel<0,0,true,false><<<gproj, 256>>>(wv, 0, h, CN, bv, nullptr, 0, v, CN, Cc, NN, Cc, 1.0f);

    // 3) scores[b,i,j] = scale * sum_c q[b,c,i] k[b,c,j]   (A^T B, both K-major)
    dim3 gsc(NN / BN, NN / BM, Bb);
    gemm_kernel<1,0,false,false><<<gsc, 256>>>(q, CN, k, CN, nullptr, nullptr, 0, sc, NN2, NN, NN, Cc, scale);

    // 4) softmax over j (rows of [B*N, N])
    softmax_kernel<<<Bb * NN, 256>>>(sc);

    // 5) ao[b,c,i] = sum_j v[b,c,j] * attn[b,i,j]   (A * B^T)
    dim3 gout(NN / BN, Cc / BM, Bb);
    gemm_kernel<0,1,false,false><<<gout, 256>>>(v, CN, sc, NN2, nullptr, nullptr, 0, ao, CN, Cc, NN, NN, 1.0f);

    // 6) out = x + Wo * ao + bo
    gemm_kernel<0,0,true,true><<<gout, 256>>>(wo, 0, ao, CN, bo, x, CN, out, CN, Cc, NN, Cc, 1.0f);
}

// round 3
// speedup vs baseline: 2.9405x; 2.9405x over previous
#include <cuda_runtime.h>
#include <math.h>
#include <stdint.h>

// ---------------- problem constants ----------------
#define Bb 4
#define Cc 512
#define NN 4096
#define GG 32
#define CPG 16

// ---------------- scratch (device globals) ----------------
__device__ __align__(128) float g_hT [(size_t)Bb*NN*Cc];   // [B,N,C] groupnorm out (tf32)
__device__ __align__(128) float g_qT [(size_t)Bb*NN*Cc];   // [B,N,C]
__device__ __align__(128) float g_kT [(size_t)Bb*NN*Cc];   // [B,N,C]
__device__ __align__(128) float g_v  [(size_t)Bb*Cc*NN];   // [B,C,N]
__device__ __align__(128) float g_aoT[(size_t)Bb*NN*Cc];   // [B,N,C]
__device__ __align__(128) float g_s  [(size_t)Bb*NN*NN];   // [B,N,N] scores/attn
__device__ __align__(128) float g_wr [4*Cc*Cc];            // tf32-rounded wq|wk|wv|wo

// ---------------- helpers ----------------
__device__ __forceinline__ uint32_t smem_u32(const void* p) {
    uint32_t a;
    asm("{ .reg .u64 t; cvta.to.shared.u64 t, %1; cvt.u32.u64 %0, t; }" : "=r"(a) : "l"(p));
    return a;
}
__device__ __forceinline__ float rna_tf32(float x) {
    float r; asm("cvt.rna.tf32.f32 %0, %1;" : "=f"(r) : "f"(x)); return r;
}
__device__ __forceinline__ void mma_tf32(float* c, const uint32_t* a, const uint32_t* b) {
    asm volatile("mma.sync.aligned.m16n8k8.row.col.f32.tf32.tf32.f32 "
        "{%0,%1,%2,%3}, {%4,%5,%6,%7}, {%8,%9}, {%0,%1,%2,%3};"
        : "+f"(c[0]), "+f"(c[1]), "+f"(c[2]), "+f"(c[3])
        : "r"(a[0]), "r"(a[1]), "r"(a[2]), "r"(a[3]), "r"(b[0]), "r"(b[1]));
}

// ---------------- block reductions ----------------
__device__ __forceinline__ float block_sum(float v, float* sh) {
    int lane = threadIdx.x & 31, w = threadIdx.x >> 5;
    #pragma unroll
    for (int o = 16; o; o >>= 1) v += __shfl_down_sync(0xffffffffu, v, o);
    if (!lane) sh[w] = v;
    __syncthreads();
    int nw = blockDim.x >> 5;
    v = (threadIdx.x < nw) ? sh[threadIdx.x] : 0.f;
    if (w == 0) {
        #pragma unroll
        for (int o = 16; o; o >>= 1) v += __shfl_down_sync(0xffffffffu, v, o);
        if (!lane) sh[0] = v;
    }
    __syncthreads();
    float r = sh[0]; __syncthreads(); return r;
}
__device__ __forceinline__ float block_max(float v, float* sh) {
    int lane = threadIdx.x & 31, w = threadIdx.x >> 5;
    #pragma unroll
    for (int o = 16; o; o >>= 1) v = fmaxf(v, __shfl_down_sync(0xffffffffu, v, o));
    if (!lane) sh[w] = v;
    __syncthreads();
    int nw = blockDim.x >> 5;
    v = (threadIdx.x < nw) ? sh[threadIdx.x] : -INFINITY;
    if (w == 0) {
        #pragma unroll
        for (int o = 16; o; o >>= 1) v = fmaxf(v, __shfl_down_sync(0xffffffffu, v, o));
        if (!lane) sh[0] = v;
    }
    __syncthreads();
    float r = sh[0]; __syncthreads(); return r;
}

// ---------------- GroupNorm -> token-major hT, tf32-rounded --------------
__global__ __launch_bounds__(256) void groupnorm_kernel(
    const float* __restrict__ x, const float* __restrict__ gamma,
    const float* __restrict__ beta, float* __restrict__ hT)
{
    __shared__ float sh[32];
    int b = blockIdx.x / GG, g = blockIdx.x % GG;
    const size_t base = ((size_t)b * Cc + (size_t)g * CPG) * NN;
    const long len = (long)CPG * NN;

    float s = 0.f, ss = 0.f;
    for (long i = threadIdx.x; i < len; i += 256) {
        float v = x[base + i]; s += v; ss += v * v;
    }
    s  = block_sum(s,  sh);
    ss = block_sum(ss, sh);
    float mean = s / (float)len;
    float var  = ss / (float)len - mean * mean;
    float inv  = rsqrtf(var + 1e-6f);

    float gm[CPG], bt[CPG];
    #pragma unroll
    for (int c = 0; c < CPG; c++) { gm[c] = gamma[g*CPG+c] * inv; bt[c] = beta[g*CPG+c]; }

    for (int i = threadIdx.x; i < NN; i += 256) {
        float vals[CPG];
        #pragma unroll
        for (int c = 0; c < CPG; c++)
            vals[c] = rna_tf32((x[base + (size_t)c*NN + i] - mean) * gm[c] + bt[c]);
        float* dst = hT + ((size_t)b*NN + i) * Cc + g*CPG;
        #pragma unroll
        for (int q = 0; q < CPG/4; q++)
            ((float4*)dst)[q] = make_float4(vals[q*4], vals[q*4+1], vals[q*4+2], vals[q*4+3]);
    }
}

// ---------------- weight rounding ----------------
__global__ __launch_bounds__(256) void round_w_kernel(
    const float* __restrict__ a, const float* __restrict__ b,
    const float* __restrict__ c, const float* __restrict__ d,
    float* __restrict__ o)
{
    int i = blockIdx.x * 256 + threadIdx.x;       // 4 * 2^18 total
    int w = i >> 18, j = i & 0x3FFFF;
    const float* src = (w == 0) ? a : (w == 1) ? b : (w == 2) ? c : d;
    o[i] = rna_tf32(src[j]);
}

// ---------------- single-pass softmax over rows of [B*N, N] -------------
__global__ __launch_bounds__(256) void softmax_kernel(float* __restrict__ s)
{
    __shared__ float sh[32];
    float* p = s + (size_t)blockIdx.x * NN;
    float v[16];
    #pragma unroll
    for (int t = 0; t < 16; t++) v[t] = p[threadIdx.x + t*256];
    float m = -INFINITY;
    #pragma unroll
    for (int t = 0; t < 16; t++) m = fmaxf(m, v[t]);
    m = block_max(m, sh);
    float sum = 0.f;
    #pragma unroll
    for (int t = 0; t < 16; t++) { v[t] = __expf(v[t] - m); sum += v[t]; }
    sum = block_sum(sum, sh);
    float inv = 1.f / sum;
    #pragma unroll
    for (int t = 0; t < 16; t++) p[threadIdx.x + t*256] = rna_tf32(v[t] * inv);
}

// ---------------- tf32 mma.sync GEMM: D[m,n] = Σk A[m,k] B[n,k] ----------
// 128x128x32 CTA tile, 256 threads, warp grid 2(M)x4(N), warp tile 64x32.
// 3-stage cp.async pipeline. A,B row-major with ld = K.
// EPI: 0 = +bias[n], round tf32  (Q/K proj)
//      1 = +bias[m], round tf32  (V proj)
//      2 = *alpha                (scores)
//      3 = round tf32            (attn*V)
//      4 = +bias[m] +res         (output proj + residual)
#define BM 128
#define BN 128
#define BK 32
#define STAGES 3
#define LDSROW 36                      // BK + 4 pad (floats)
#define TILE_F (BM * LDSROW)           // floats per stage per operand
#define SMEM_REQ (2 * STAGES * TILE_F * 4)

__device__ __forceinline__ void load_tile(const float* g, float* s, int tid, int ld) {
    int cq = (tid & 7) * 4;            // k-offset (floats)
    int r0 = tid >> 3;                 // 0..31
    #pragma unroll
    for (int i = 0; i < 4; i++) {
        int r = r0 + i * 32;
        uint32_t dst = smem_u32(s + r * LDSROW + cq);
        const float* src = g + (size_t)r * ld + cq;
        asm volatile("cp.async.cg.shared.global [%0], [%1], 16;" :: "r"(dst), "l"(src));
    }
}

template<int EPI>
__global__ __launch_bounds__(256, 1) void mma_gemm(
    const float* __restrict__ A, long zA,
    const float* __restrict__ B, long zB,
    const float* __restrict__ bias,
    const float* __restrict__ res, long zR,
    float* __restrict__ C, long zC, int ldC,
    int K, float alpha)
{
    extern __shared__ float smem[];
    float* As = smem;
    float* Bs = smem + STAGES * TILE_F;

    const int tid = threadIdx.x;
    const int m0 = blockIdx.y * BM, n0 = blockIdx.x * BN, bz = blockIdx.z;

    A += (size_t)bz * zA + (size_t)m0 * K;
    B += (size_t)bz * zB + (size_t)n0 * K;

    const int KT = K / BK;

    #pragma unroll
    for (int st = 0; st < STAGES - 1; st++) {
        load_tile(A + st * BK, As + st * TILE_F, tid, K);
        load_tile(B + st * BK, Bs + st * TILE_F, tid, K);
        asm volatile("cp.async.commit_group;" ::: "memory");
    }

    const int lane = tid & 31, wid = tid >> 5;
    const int gid = lane >> 2, tig = lane & 3;
    const int wm = (wid & 1) * 64;     // warp M offset
    const int wn = (wid >> 1) * 32;    // warp N offset

    float c[4][4][4];
    #pragma unroll
    for (int im = 0; im < 4; im++)
        #pragma unroll
        for (int in = 0; in < 4; in++)
            #pragma unroll
            for (int r = 0; r < 4; r++) c[im][in][r] = 0.f;

    for (int kt = 0; kt < KT; kt++) {
        asm volatile("cp.async.wait_group %0;" :: "n"(STAGES - 2) : "memory");
        __syncthreads();

        if (kt + STAGES - 1 < KT) {
            int st = (kt + STAGES - 1) % STAGES;
            load_tile(A + (kt + STAGES - 1) * BK, As + st * TILE_F, tid, K);
            load_tile(B + (kt + STAGES - 1) * BK, Bs + st * TILE_F, tid, K);
        }
        asm volatile("cp.async.commit_group;" ::: "memory");

        const float* as = As + (kt % STAGES) * TILE_F;
        const float* bs = Bs + (kt % STAGES) * TILE_F;

        #pragma unroll
        for (int k8 = 0; k8 < BK; k8 += 8) {
            uint32_t af[4][4], bf[4][2];
            #pragma unroll
            for (int im = 0; im < 4; im++) {
                const float* p = as + (wm + im*16 + gid) * LDSROW + k8 + tig;
                af[im][0] = __float_as_uint(p[0]);
                af[im][1] = __float_as_uint(p[8 * LDSROW]);
                af[im][2] = __float_as_uint(p[4]);
                af[im][3] = __float_as_uint(p[8 * LDSROW + 4]);
            }
            #pragma unroll
            for (int in = 0; in < 4; in++) {
                const float* p = bs + (wn + in*8 + gid) * LDSROW + k8 + tig;
                bf[in][0] = __float_as_uint(p[0]);
                bf[in][1] = __float_as_uint(p[4]);
            }
            #pragma unroll
            for (int im = 0; im < 4; im++)
                #pragma unroll
                for (int in = 0; in < 4; in++)
                    mma_tf32(c[im][in], af[im], bf[in]);
        }
        __syncthreads();
    }

    // ---- epilogue ----
    float* Cw = C + (size_t)bz * zC + (size_t)(m0 + wm) * ldC + n0 + wn;
    const float* Rw = (EPI == 4) ? res + (size_t)bz * zR + (size_t)(m0 + wm) * ldC + n0 + wn : nullptr;

    #pragma unroll
    for (int im = 0; im < 4; im++) {
        int r0 = im * 16 + gid;
        float bm0 = 0.f, bm1 = 0.f;
        if (EPI == 1 || EPI == 4) {
            bm0 = __ldg(bias + m0 + wm + r0);
            bm1 = __ldg(bias + m0 + wm + r0 + 8);
        }
        #pragma unroll
        for (int in = 0; in < 4; in++) {
            int col = in * 8 + tig * 2;
            float bn0 = 0.f, bn1 = 0.f;
            if (EPI == 0) {
                bn0 = __ldg(bias + n0 + wn + col);
                bn1 = __ldg(bias + n0 + wn + col + 1);
            }
            float v0 = c[im][in][0], v1 = c[im][in][1];
            float v2 = c[im][in][2], v3 = c[im][in][3];
            if (EPI == 0) {
                v0 = rna_tf32(v0 + bn0); v1 = rna_tf32(v1 + bn1);
                v2 = rna_tf32(v2 + bn0); v3 = rna_tf32(v3 + bn1);
            } else if (EPI == 1) {
                v0 = rna_tf32(v0 + bm0); v1 = rna_tf32(v1 + bm0);
                v2 = rna_tf32(v2 + bm1); v3 = rna_tf32(v3 + bm1);
            } else if (EPI == 2) {
                v0 *= alpha; v1 *= alpha; v2 *= alpha; v3 *= alpha;
            } else if (EPI == 3) {
                v0 = rna_tf32(v0); v1 = rna_tf32(v1);
                v2 = rna_tf32(v2); v3 = rna_tf32(v3);
            } else {
                const float* ra = Rw + (size_t)r0 * ldC + col;
                const float* rb = Rw + (size_t)(r0 + 8) * ldC + col;
                v0 += bm0 + ra[0]; v1 += bm0 + ra[1];
                v2 += bm1 + rb[0]; v3 += bm1 + rb[1];
            }
            *(float2*)(Cw + (size_t)r0 * ldC + col)       = make_float2(v0, v1);
            *(float2*)(Cw + (size_t)(r0 + 8) * ldC + col) = make_float2(v2, v3);
        }
    }
}

// ---------------- launch ----------------
extern "C" void kernel_launch(void* const* d_in, const int* in_sizes, int n_in,
                              void* d_out, int out_size)
{
    const float* x     = (const float*)d_in[0];
    const float* gamma = (const float*)d_in[1];
    const float* beta  = (const float*)d_in[2];
    const float* wq    = (const float*)d_in[3];
    const float* bq    = (const float*)d_in[4];
    const float* wk    = (const float*)d_in[5];
    const float* bk    = (const float*)d_in[6];
    const float* wv    = (const float*)d_in[7];
    const float* bv    = (const float*)d_in[8];
    const float* wo    = (const float*)d_in[9];
    const float* bo    = (const float*)d_in[10];
    float* out = (float*)d_out;

    float *hT, *qT, *kT, *v, *aoT, *s, *wr;
    cudaGetSymbolAddress((void**)&hT,  g_hT);
    cudaGetSymbolAddress((void**)&qT,  g_qT);
    cudaGetSymbolAddress((void**)&kT,  g_kT);
    cudaGetSymbolAddress((void**)&v,   g_v);
    cudaGetSymbolAddress((void**)&aoT, g_aoT);
    cudaGetSymbolAddress((void**)&s,   g_s);
    cudaGetSymbolAddress((void**)&wr,  g_wr);

    static bool attr_done = false;
    if (!attr_done) {
        cudaFuncSetAttribute(mma_gemm<0>, cudaFuncAttributeMaxDynamicSharedMemorySize, SMEM_REQ);
        cudaFuncSetAttribute(mma_gemm<1>, cudaFuncAttributeMaxDynamicSharedMemorySize, SMEM_REQ);
        cudaFuncSetAttribute(mma_gemm<2>, cudaFuncAttributeMaxDynamicSharedMemorySize, SMEM_REQ);
        cudaFuncSetAttribute(mma_gemm<3>, cudaFuncAttributeMaxDynamicSharedMemorySize, SMEM_REQ);
        cudaFuncSetAttribute(mma_gemm<4>, cudaFuncAttributeMaxDynamicSharedMemorySize, SMEM_REQ);
        attr_done = true;
    }

    const long CN  = (long)Cc * NN;
    const long NC  = (long)NN * Cc;
    const long NN2 = (long)NN * NN;
    const float scale = 1.0f / sqrtf((float)Cc);

    // 1) GroupNorm -> hT [B,N,C] (tf32)
    groupnorm_kernel<<<Bb * GG, 256>>>(x, gamma, beta, hT);
    // 2) round weights to tf32
    round_w_kernel<<<4 * Cc * Cc / 256, 256>>>(wq, wk, wv, wo, wr);

    // 3) qT[i,d] = Σc hT[i,c] wq[d,c] + bq[d]
    mma_gemm<0><<<dim3(Cc/BN, NN/BM, Bb), 256, SMEM_REQ>>>(
        hT, NC, wr + 0*Cc*Cc, 0, bq, nullptr, 0, qT, NC, Cc, Cc, 0.f);
    // 4) kT
    mma_gemm<0><<<dim3(Cc/BN, NN/BM, Bb), 256, SMEM_REQ>>>(
        hT, NC, wr + 1*Cc*Cc, 0, bk, nullptr, 0, kT, NC, Cc, Cc, 0.f);
    // 5) v[d,j] = Σc wv[d,c] hT[j,c] + bv[d]
    mma_gemm<1><<<dim3(NN/BN, Cc/BM, Bb), 256, SMEM_REQ>>>(
        wr + 2*Cc*Cc, 0, hT, NC, bv, nullptr, 0, v, CN, NN, Cc, 0.f);
    // 6) scores[i,j] = scale * Σc qT[i,c] kT[j,c]
    mma_gemm<2><<<dim3(NN/BN, NN/BM, Bb), 256, SMEM_REQ>>>(
        qT, NC, kT, NC, nullptr, nullptr, 0, s, NN2, NN, Cc, scale);
    // 7) softmax rows (tf32-rounded output)
    softmax_kernel<<<Bb * NN, 256>>>(s);
    // 8) aoT[i,c] = Σj attn[i,j] v[c,j]
    mma_gemm<3><<<dim3(Cc/BN, NN/BM, Bb), 256, SMEM_REQ>>>(
        s, NN2, v, CN, nullptr, nullptr, 0, aoT, NC, Cc, NN, 0.f);
    // 9) out[c,i] = x[c,i] + Σd wo[c,d] aoT[i,d] + bo[c]
    mma_gemm<4><<<dim3(NN/BN, Cc/BM, Bb), 256, SMEM_REQ>>>(
        wr + 3*Cc*Cc, 0, aoT, NC, bo, x, CN, out, CN, NN, Cc, 0.f);
}

// round 4
// speedup vs baseline: 3.3960x; 1.1549x over previous
#include <cuda_runtime.h>
#include <math.h>
#include <stdint.h>

// ---------------- problem constants ----------------
#define Bb 4
#define Cc 512
#define NN 4096
#define GG 32
#define CPG 16

// ---------------- scratch (device globals) ----------------
__device__ __align__(128) float g_hT  [(size_t)Bb*NN*Cc];    // [B,N,C] groupnorm out (tf32)
__device__ __align__(128) float g_qkT [(size_t)Bb*NN*2*Cc];  // [B,N,2C]: q|k per token
__device__ __align__(128) float g_v   [(size_t)Bb*Cc*NN];    // [B,C,N]
__device__ __align__(128) float g_aoT [(size_t)Bb*NN*Cc];    // [B,N,C]
__device__ __align__(128) float g_s   [(size_t)Bb*NN*NN];    // [B,N,N] scores/attn
__device__ __align__(128) float g_wr  [4*Cc*Cc];             // tf32 wq|wk|wv|wo
__device__ __align__(128) float g_bqk [2*Cc];                // bq|bk

// ---------------- helpers ----------------
__device__ __forceinline__ uint32_t smem_u32(const void* p) {
    uint32_t a;
    asm("{ .reg .u64 t; cvta.to.shared.u64 t, %1; cvt.u32.u64 %0, t; }" : "=r"(a) : "l"(p));
    return a;
}
__device__ __forceinline__ float rna_tf32(float x) {
    float r; asm("cvt.rna.tf32.f32 %0, %1;" : "=f"(r) : "f"(x)); return r;
}
__device__ __forceinline__ void mma_tf32(float* c, const uint32_t* a, const uint32_t* b) {
    asm volatile("mma.sync.aligned.m16n8k8.row.col.f32.tf32.tf32.f32 "
        "{%0,%1,%2,%3}, {%4,%5,%6,%7}, {%8,%9}, {%0,%1,%2,%3};"
        : "+f"(c[0]), "+f"(c[1]), "+f"(c[2]), "+f"(c[3])
        : "r"(a[0]), "r"(a[1]), "r"(a[2]), "r"(a[3]), "r"(b[0]), "r"(b[1]));
}

// ---------------- block reductions ----------------
__device__ __forceinline__ float block_sum(float v, float* sh) {
    int lane = threadIdx.x & 31, w = threadIdx.x >> 5;
    #pragma unroll
    for (int o = 16; o; o >>= 1) v += __shfl_down_sync(0xffffffffu, v, o);
    if (!lane) sh[w] = v;
    __syncthreads();
    int nw = blockDim.x >> 5;
    v = (threadIdx.x < nw) ? sh[threadIdx.x] : 0.f;
    if (w == 0) {
        #pragma unroll
        for (int o = 16; o; o >>= 1) v += __shfl_down_sync(0xffffffffu, v, o);
        if (!lane) sh[0] = v;
    }
    __syncthreads();
    float r = sh[0]; __syncthreads(); return r;
}
__device__ __forceinline__ float block_max(float v, float* sh) {
    int lane = threadIdx.x & 31, w = threadIdx.x >> 5;
    #pragma unroll
    for (int o = 16; o; o >>= 1) v = fmaxf(v, __shfl_down_sync(0xffffffffu, v, o));
    if (!lane) sh[w] = v;
    __syncthreads();
    int nw = blockDim.x >> 5;
    v = (threadIdx.x < nw) ? sh[threadIdx.x] : -INFINITY;
    if (w == 0) {
        #pragma unroll
        for (int o = 16; o; o >>= 1) v = fmaxf(v, __shfl_down_sync(0xffffffffu, v, o));
        if (!lane) sh[0] = v;
    }
    __syncthreads();
    float r = sh[0]; __syncthreads(); return r;
}

// ---------------- GroupNorm -> token-major hT, tf32-rounded --------------
__global__ __launch_bounds__(256) void groupnorm_kernel(
    const float* __restrict__ x, const float* __restrict__ gamma,
    const float* __restrict__ beta, float* __restrict__ hT)
{
    __shared__ float sh[32];
    int b = blockIdx.x / GG, g = blockIdx.x % GG;
    const size_t base = ((size_t)b * Cc + (size_t)g * CPG) * NN;
    const long len = (long)CPG * NN;

    float s = 0.f, ss = 0.f;
    for (long i = threadIdx.x; i < len; i += 256) {
        float v = x[base + i]; s += v; ss += v * v;
    }
    s  = block_sum(s,  sh);
    ss = block_sum(ss, sh);
    float mean = s / (float)len;
    float var  = ss / (float)len - mean * mean;
    float inv  = rsqrtf(var + 1e-6f);

    float gm[CPG], bt[CPG];
    #pragma unroll
    for (int c = 0; c < CPG; c++) { gm[c] = gamma[g*CPG+c] * inv; bt[c] = beta[g*CPG+c]; }

    for (int i = threadIdx.x; i < NN; i += 256) {
        float vals[CPG];
        #pragma unroll
        for (int c = 0; c < CPG; c++)
            vals[c] = rna_tf32((x[base + (size_t)c*NN + i] - mean) * gm[c] + bt[c]);
        float* dst = hT + ((size_t)b*NN + i) * Cc + g*CPG;
        #pragma unroll
        for (int q = 0; q < CPG/4; q++)
            ((float4*)dst)[q] = make_float4(vals[q*4], vals[q*4+1], vals[q*4+2], vals[q*4+3]);
    }
}

// ---------------- weight rounding + bias concat ----------------
__global__ __launch_bounds__(256) void round_w_kernel(
    const float* __restrict__ a, const float* __restrict__ b,
    const float* __restrict__ c, const float* __restrict__ d,
    float* __restrict__ o)
{
    int i = blockIdx.x * 256 + threadIdx.x;
    int w = i >> 18, j = i & 0x3FFFF;
    const float* src = (w == 0) ? a : (w == 1) ? b : (w == 2) ? c : d;
    o[i] = rna_tf32(src[j]);
}
__global__ __launch_bounds__(256) void concat_bias_kernel(
    const float* __restrict__ a, const float* __restrict__ b, float* __restrict__ o)
{
    int i = blockIdx.x * 256 + threadIdx.x;
    o[i] = (i < Cc) ? a[i] : b[i - Cc];
}

// ---------------- single-pass softmax over rows of [B*N, N] -------------
__global__ __launch_bounds__(256) void softmax_kernel(float* __restrict__ s)
{
    __shared__ float sh[32];
    float* p = s + (size_t)blockIdx.x * NN;
    float v[16];
    #pragma unroll
    for (int t = 0; t < 16; t++) v[t] = p[threadIdx.x + t*256];
    float m = -INFINITY;
    #pragma unroll
    for (int t = 0; t < 16; t++) m = fmaxf(m, v[t]);
    m = block_max(m, sh);
    float sum = 0.f;
    #pragma unroll
    for (int t = 0; t < 16; t++) { v[t] = __expf(v[t] - m); sum += v[t]; }
    sum = block_sum(sum, sh);
    float inv = 1.f / sum;
    #pragma unroll
    for (int t = 0; t < 16; t++) p[threadIdx.x + t*256] = rna_tf32(v[t] * inv);
}

// ---------------- tf32 mma.sync GEMM: D[m,n] = Σk A[m,k] B[n,k] ----------
// CTA tile 128(M) x 256(N) x 32(K), 256 threads, warp grid 2(M)x4(N),
// warp tile 64x64 (32 MMAs per 32 LDS.32 per k8). 3-stage cp.async pipeline.
// EPI: 0 = +bias[n], round tf32   (merged QK proj)
//      1 = +bias[m], round tf32   (V proj)
//      2 = *alpha                 (scores)
//      3 = round tf32             (attn*V)
//      4 = +bias[m] +res          (output proj + residual)
#define BM 128
#define BN 256
#define BK 32
#define STAGES 3
#define LDSROW 36
#define ATILE_F (BM * LDSROW)
#define BTILE_F (BN * LDSROW)
#define STAGE_F (ATILE_F + BTILE_F)
#define SMEM_REQ (STAGES * STAGE_F * 4)

template<int ROWS>
__device__ __forceinline__ void load_tile(const float* g, float* s, int tid, int ld) {
    int cq = (tid & 7) * 4;
    int r0 = tid >> 3;
    #pragma unroll
    for (int i = 0; i < ROWS / 32; i++) {
        int r = r0 + i * 32;
        uint32_t dst = smem_u32(s + r * LDSROW + cq);
        const float* src = g + (size_t)r * ld + cq;
        asm volatile("cp.async.cg.shared.global [%0], [%1], 16;" :: "r"(dst), "l"(src));
    }
}

template<int EPI>
__global__ __launch_bounds__(256, 1) void mma_gemm(
    const float* __restrict__ A, long zA, int ldA,
    const float* __restrict__ B, long zB, int ldB,
    const float* __restrict__ bias,
    const float* __restrict__ res, long zR,
    float* __restrict__ C, long zC, int ldC,
    int K, float alpha)
{
    extern __shared__ float smem[];

    const int tid = threadIdx.x;
    const int m0 = blockIdx.y * BM, n0 = blockIdx.x * BN, bz = blockIdx.z;

    A += (size_t)bz * zA + (size_t)m0 * ldA;
    B += (size_t)bz * zB + (size_t)n0 * ldB;

    const int KT = K / BK;

    #pragma unroll
    for (int st = 0; st < STAGES - 1; st++) {
        load_tile<BM>(A + st * BK, smem + st * STAGE_F, tid, ldA);
        load_tile<BN>(B + st * BK, smem + st * STAGE_F + ATILE_F, tid, ldB);
        asm volatile("cp.async.commit_group;" ::: "memory");
    }

    const int lane = tid & 31, wid = tid >> 5;
    const int gid = lane >> 2, tig = lane & 3;
    const int wm = (wid & 1) * 64;     // warp M offset (2 warps)
    const int wn = (wid >> 1) * 64;    // warp N offset (4 warps)

    float c[4][8][4];
    #pragma unroll
    for (int im = 0; im < 4; im++)
        #pragma unroll
        for (int in = 0; in < 8; in++)
            #pragma unroll
            for (int r = 0; r < 4; r++) c[im][in][r] = 0.f;

    for (int kt = 0; kt < KT; kt++) {
        asm volatile("cp.async.wait_group %0;" :: "n"(STAGES - 2) : "memory");
        __syncthreads();

        if (kt + STAGES - 1 < KT) {
            int st = (kt + STAGES - 1) % STAGES;
            load_tile<BM>(A + (kt + STAGES - 1) * BK, smem + st * STAGE_F, tid, ldA);
            load_tile<BN>(B + (kt + STAGES - 1) * BK, smem + st * STAGE_F + ATILE_F, tid, ldB);
        }
        asm volatile("cp.async.commit_group;" ::: "memory");

        const float* as = smem + (kt % STAGES) * STAGE_F;
        const float* bs = as + ATILE_F;

        #pragma unroll
        for (int k8 = 0; k8 < BK; k8 += 8) {
            uint32_t af[4][4], bf[8][2];
            #pragma unroll
            for (int im = 0; im < 4; im++) {
                const float* p = as + (wm + im*16 + gid) * LDSROW + k8 + tig;
                af[im][0] = __float_as_uint(p[0]);
                af[im][1] = __float_as_uint(p[8 * LDSROW]);
                af[im][2] = __float_as_uint(p[4]);
                af[im][3] = __float_as_uint(p[8 * LDSROW + 4]);
            }
            #pragma unroll
            for (int in = 0; in < 8; in++) {
                const float* p = bs + (wn + in*8 + gid) * LDSROW + k8 + tig;
                bf[in][0] = __float_as_uint(p[0]);
                bf[in][1] = __float_as_uint(p[4]);
            }
            #pragma unroll
            for (int im = 0; im < 4; im++)
                #pragma unroll
                for (int in = 0; in < 8; in++)
                    mma_tf32(c[im][in], af[im], bf[in]);
        }
        __syncthreads();
    }

    // ---- epilogue ----
    float* Cw = C + (size_t)bz * zC + (size_t)(m0 + wm) * ldC + n0 + wn;
    const float* Rw = (EPI == 4) ? res + (size_t)bz * zR + (size_t)(m0 + wm) * ldC + n0 + wn : nullptr;

    #pragma unroll
    for (int im = 0; im < 4; im++) {
        int r0 = im * 16 + gid;
        float bm0 = 0.f, bm1 = 0.f;
        if (EPI == 1 || EPI == 4) {
            bm0 = __ldg(bias + m0 + wm + r0);
            bm1 = __ldg(bias + m0 + wm + r0 + 8);
        }
        #pragma unroll
        for (int in = 0; in < 8; in++) {
            int col = in * 8 + tig * 2;
            float bn0 = 0.f, bn1 = 0.f;
            if (EPI == 0) {
                bn0 = __ldg(bias + n0 + wn + col);
                bn1 = __ldg(bias + n0 + wn + col + 1);
            }
            float v0 = c[im][in][0], v1 = c[im][in][1];
            float v2 = c[im][in][2], v3 = c[im][in][3];
            if (EPI == 0) {
                v0 = rna_tf32(v0 + bn0); v1 = rna_tf32(v1 + bn1);
                v2 = rna_tf32(v2 + bn0); v3 = rna_tf32(v3 + bn1);
            } else if (EPI == 1) {
                v0 = rna_tf32(v0 + bm0); v1 = rna_tf32(v1 + bm0);
                v2 = rna_tf32(v2 + bm1); v3 = rna_tf32(v3 + bm1);
            } else if (EPI == 2) {
                v0 *= alpha; v1 *= alpha; v2 *= alpha; v3 *= alpha;
            } else if (EPI == 3) {
                v0 = rna_tf32(v0); v1 = rna_tf32(v1);
                v2 = rna_tf32(v2); v3 = rna_tf32(v3);
            } else {
                const float* ra = Rw + (size_t)r0 * ldC + col;
                const float* rb = Rw + (size_t)(r0 + 8) * ldC + col;
                v0 += bm0 + ra[0]; v1 += bm0 + ra[1];
                v2 += bm1 + rb[0]; v3 += bm1 + rb[1];
            }
            *(float2*)(Cw + (size_t)r0 * ldC + col)       = make_float2(v0, v1);
            *(float2*)(Cw + (size_t)(r0 + 8) * ldC + col) = make_float2(v2, v3);
        }
    }
}

// ---------------- launch ----------------
extern "C" void kernel_launch(void* const* d_in, const int* in_sizes, int n_in,
                              void* d_out, int out_size)
{
    const float* x     = (const float*)d_in[0];
    const float* gamma = (const float*)d_in[1];
    const float* beta  = (const float*)d_in[2];
    const float* wq    = (const float*)d_in[3];
    const float* bq    = (const float*)d_in[4];
    const float* wk    = (const float*)d_in[5];
    const float* bk    = (const float*)d_in[6];
    const float* wv    = (const float*)d_in[7];
    const float* bv    = (const float*)d_in[8];
    const float* wo    = (const float*)d_in[9];
    const float* bo    = (const float*)d_in[10];
    float* out = (float*)d_out;

    float *hT, *qkT, *v, *aoT, *s, *wr, *bqk;
    cudaGetSymbolAddress((void**)&hT,  g_hT);
    cudaGetSymbolAddress((void**)&qkT, g_qkT);
    cudaGetSymbolAddress((void**)&v,   g_v);
    cudaGetSymbolAddress((void**)&aoT, g_aoT);
    cudaGetSymbolAddress((void**)&s,   g_s);
    cudaGetSymbolAddress((void**)&wr,  g_wr);
    cudaGetSymbolAddress((void**)&bqk, g_bqk);

    static bool attr_done = false;
    if (!attr_done) {
        cudaFuncSetAttribute(mma_gemm<0>, cudaFuncAttributeMaxDynamicSharedMemorySize, SMEM_REQ);
        cudaFuncSetAttribute(mma_gemm<1>, cudaFuncAttributeMaxDynamicSharedMemorySize, SMEM_REQ);
        cudaFuncSetAttribute(mma_gemm<2>, cudaFuncAttributeMaxDynamicSharedMemorySize, SMEM_REQ);
        cudaFuncSetAttribute(mma_gemm<3>, cudaFuncAttributeMaxDynamicSharedMemorySize, SMEM_REQ);
        cudaFuncSetAttribute(mma_gemm<4>, cudaFuncAttributeMaxDynamicSharedMemorySize, SMEM_REQ);
        attr_done = true;
    }

    const long CN  = (long)Cc * NN;      // [C,N] batch stride
    const long NC  = (long)NN * Cc;      // [N,C] batch stride
    const long NC2 = (long)NN * 2 * Cc;  // [N,2C] batch stride
    const long NN2 = (long)NN * NN;
    const float scale = 1.0f / sqrtf((float)Cc);

    // 1) GroupNorm -> hT [B,N,C] (tf32)
    groupnorm_kernel<<<Bb * GG, 256>>>(x, gamma, beta, hT);
    // 2) round weights, concat q/k biases
    round_w_kernel<<<4 * Cc * Cc / 256, 256>>>(wq, wk, wv, wo, wr);
    concat_bias_kernel<<<2 * Cc / 256, 256>>>(bq, bk, bqk);

    // 3) merged QK proj: qkT[i, d] = Σc hT[i,c] (wq|wk)[d,c] + (bq|bk)[d]
    mma_gemm<0><<<dim3(2*Cc/BN, NN/BM, Bb), 256, SMEM_REQ>>>(
        hT, NC, Cc, wr, 0, Cc, bqk, nullptr, 0, qkT, NC2, 2*Cc, Cc, 0.f);
    // 4) v[d,j] = Σc wv[d,c] hT[j,c] + bv[d]
    mma_gemm<1><<<dim3(NN/BN, Cc/BM, Bb), 256, SMEM_REQ>>>(
        wr + 2*Cc*Cc, 0, Cc, hT, NC, Cc, bv, nullptr, 0, v, CN, NN, Cc, 0.f);
    // 5) scores[i,j] = scale * Σc q[i,c] k[j,c]   (q = qkT[:, :512], k = qkT[:, 512:])
    mma_gemm<2><<<dim3(NN/BN, NN/BM, Bb), 256, SMEM_REQ>>>(
        qkT, NC2, 2*Cc, qkT + Cc, NC2, 2*Cc, nullptr, nullptr, 0, s, NN2, NN, Cc, scale);
    // 6) softmax rows (tf32-rounded output)
    softmax_kernel<<<Bb * NN, 256>>>(s);
    // 7) aoT[i,c] = Σj attn[i,j] v[c,j]
    mma_gemm<3><<<dim3(Cc/BN, NN/BM, Bb), 256, SMEM_REQ>>>(
        s, NN2, NN, v, CN, NN, nullptr, nullptr, 0, aoT, NC, Cc, NN, 0.f);
    // 8) out[c,i] = x[c,i] + Σd wo[c,d] aoT[i,d] + bo[c]
    mma_gemm<4><<<dim3(NN/BN, Cc/BM, Bb), 256, SMEM_REQ>>>(
        wr + 3*Cc*Cc, 0, Cc, aoT, NC, Cc, bo, x, CN, out, CN, NN, Cc, 0.f);
}